// round 15
// baseline (speedup 1.0000x reference)
#include <cuda_runtime.h>

// Laplacian pyramid, 5 levels, (16,3,1024,1024) fp32, edge-clamp padding.
// Levels 0-1: warp-persistent sliding-window kernel, software-pipelined
// (depth-1 prefetch). Level 0 SEG=64 (vertical halo 1.05x).
// Levels 2-3: block-tiled fused kernel; level 3 uses TCY=8 for more CTAs.

#define NIMG 48  // 16 * 3

__device__ float g_g1[NIMG * 512 * 512];
__device__ float g_g2[NIMG * 256 * 256];
__device__ float g_g3[NIMG * 128 * 128];

// ---------------------------------------------------------------------------
// Warp-persistent pipelined kernel (big levels).
// ---------------------------------------------------------------------------
template <int Hc, int Wc, int SEG>
__global__ __launch_bounds__(256) void lpyr_warp_kernel(
    const float* __restrict__ fine,
    float* __restrict__ coarse_out,
    float* __restrict__ lap_out)
{
    constexpr int H = 2 * Hc, W = 2 * Wc;
    constexpr int NSTRIP = Wc / 64;            // 128 fine cols per strip

    const int lane = threadIdx.x;
    const int wg   = blockIdx.x * 8 + threadIdx.y;
    const int strip = wg % NSTRIP;
    const int seg   = wg / NSTRIP;
    const int img   = blockIdx.z;
    const int r0    = seg * SEG;
    const int base_f = strip * 128;
    const bool stripL = (strip == 0);
    const bool stripR = (strip == NSTRIP - 1);

    const float* fp = fine + (size_t)img * H * W;
    float* cop = coarse_out + (size_t)img * Hc * Wc;
    float* lop = lap_out + (size_t)img * H * W;

    const float h0 = 0.0625f, h1 = 0.25f, h2 = 0.375f;
    const float hwv[5] = {h0, h1, h2, h1, h0};

    auto loadraw = [&](int r, float4& raw, float4& eraw) {
        r = r < 0 ? 0 : (r >= H ? H - 1 : r);
        const float* rp = fp + (size_t)r * W + base_f;
        raw = *(const float4*)(rp + 4 * lane);
        if (lane == 0 && !stripL)  eraw = *(const float4*)(rp - 4);
        if (lane == 31 && !stripR) eraw = *(const float4*)(rp + 128);
    };

    auto filterrow = [&](float4 buf, float4 er, float& hv0, float& hv1, float& hvE) {
        float4 eL = make_float4(buf.x, buf.x, buf.x, buf.x);
        float4 eR = make_float4(buf.w, buf.w, buf.w, buf.w);
        if (lane == 0 && !stripL)  eL = er;
        if (lane == 31 && !stripR) eR = er;
        float xl2 = __shfl_up_sync(0xffffffffu, buf.z, 1);
        float xl1 = __shfl_up_sync(0xffffffffu, buf.w, 1);
        float xr1 = __shfl_down_sync(0xffffffffu, buf.x, 1);
        if (lane == 0)  { xl2 = eL.z; xl1 = eL.w; }
        if (lane == 31) { xr1 = eR.x; }
        hv0 = fmaf(h0, xl2 + buf.z, fmaf(h1, xl1 + buf.y, h2 * buf.x));
        hv1 = fmaf(h0, buf.x + xr1, fmaf(h1, buf.y + buf.w, h2 * buf.z));
        float hvEL = fmaf(h0, eL.x + buf.x, fmaf(h1, eL.y + eL.w, h2 * eL.z));
        float hvER = fmaf(h0, buf.z + eR.z, fmaf(h1, buf.w + eR.y, h2 * eR.x));
        hvE = (lane == 31) ? hvER : hvEL;
    };

    float wh0[5], wh1[5], whE[5];
    float4 keepA1, keepB1, keepB2;

    {
        float4 rtmp, etmp;
#pragma unroll
        for (int a = 0; a < 5; a++) {
            loadraw(2 * r0 - 4 + a, rtmp, etmp);
            filterrow(rtmp, etmp, wh0[a], wh1[a], whE[a]);
        }
        keepB1 = rtmp;
        keepA1 = rtmp; keepB2 = rtmp;
    }

    float4 hist1, hist2;
    {
        float c0 = 0.f, c1 = 0.f, cE = 0.f;
#pragma unroll
        for (int a = 0; a < 5; a++) {
            c0 = fmaf(hwv[a], wh0[a], c0);
            c1 = fmaf(hwv[a], wh1[a], c1);
            cE = fmaf(hwv[a], whE[a], cE);
        }
        float cLh = __shfl_up_sync(0xffffffffu, c1, 1);
        float cRh = __shfl_down_sync(0xffffffffu, c0, 1);
        if (lane == 0)  cLh = stripL ? c0 : cE;
        if (lane == 31) cRh = stripR ? c1 : cE;
        hist1 = make_float4(cLh, c0, c1, cRh);
        hist2 = hist1;
    }

    // depth-1 software pipeline: loads for iteration ci already in flight
    float4 nA, nB, nAe, nBe;
    loadraw(2 * r0 + 1, nA, nAe);
    loadraw(2 * r0 + 2, nB, nBe);

#pragma unroll 1
    for (int ci = r0; ci <= r0 + SEG; ci++) {
        float4 rawA = nA, rawB = nB, rAe = nAe, rBe = nBe;
        if (ci < r0 + SEG) {                   // prefetch next iteration
            loadraw(2 * ci + 3, nA, nAe);
            loadraw(2 * ci + 4, nB, nBe);
        }

        float a0, a1, aE, b0, b1, bE;
        filterrow(rawA, rAe, a0, a1, aE);
        filterrow(rawB, rBe, b0, b1, bE);

        wh0[0] = wh0[2]; wh0[1] = wh0[3]; wh0[2] = wh0[4]; wh0[3] = a0; wh0[4] = b0;
        wh1[0] = wh1[2]; wh1[1] = wh1[3]; wh1[2] = wh1[4]; wh1[3] = a1; wh1[4] = b1;
        whE[0] = whE[2]; whE[1] = whE[3]; whE[2] = whE[4]; whE[3] = aE; whE[4] = bE;

        float c0 = 0.f, c1 = 0.f, cE = 0.f;
#pragma unroll
        for (int a = 0; a < 5; a++) {
            c0 = fmaf(hwv[a], wh0[a], c0);
            c1 = fmaf(hwv[a], wh1[a], c1);
            cE = fmaf(hwv[a], whE[a], cE);
        }
        float cLh = __shfl_up_sync(0xffffffffu, c1, 1);
        float cRh = __shfl_down_sync(0xffffffffu, c0, 1);
        if (lane == 0)  cLh = stripL ? c0 : cE;   // image edge: clamp on COARSE grid
        if (lane == 31) cRh = stripR ? c1 : cE;
        float4 cur = make_float4(cLh, c0, c1, cRh);

        if (ci < r0 + SEG)
            *(float2*)(cop + (size_t)ci * Wc + (base_f >> 1) + 2 * lane) =
                make_float2(c0, c1);

        if (ci > r0) {
            const int cp = ci - 1;
            float4 A = (cp == 0) ? hist1 : hist2;
            float4 B = hist1;
            float4 C = (cp == Hc - 1) ? hist1 : cur;

            float rE0 = fmaf(0.125f, A.x + C.x, 0.75f * B.x);
            float rE1 = fmaf(0.125f, A.y + C.y, 0.75f * B.y);
            float rE2 = fmaf(0.125f, A.z + C.z, 0.75f * B.z);
            float rE3 = fmaf(0.125f, A.w + C.w, 0.75f * B.w);
            float rO0 = 0.5f * (B.x + C.x);
            float rO1 = 0.5f * (B.y + C.y);
            float rO2 = 0.5f * (B.z + C.z);
            float rO3 = 0.5f * (B.w + C.w);

            float oE0 = fmaf(0.125f, rE0 + rE2, 0.75f * rE1);
            float oE1 = 0.5f * (rE1 + rE2);
            float oE2 = fmaf(0.125f, rE1 + rE3, 0.75f * rE2);
            float oE3 = 0.5f * (rE2 + rE3);
            float oO0 = fmaf(0.125f, rO0 + rO2, 0.75f * rO1);
            float oO1 = 0.5f * (rO1 + rO2);
            float oO2 = fmaf(0.125f, rO1 + rO3, 0.75f * rO2);
            float oO3 = 0.5f * (rO2 + rO3);

            size_t top = (size_t)(2 * cp) * W + base_f + 4 * lane;
            __stcs((float4*)(lop + top),
                   make_float4(keepB2.x - oE0, keepB2.y - oE1,
                               keepB2.z - oE2, keepB2.w - oE3));
            __stcs((float4*)(lop + top + W),
                   make_float4(keepA1.x - oO0, keepA1.y - oO1,
                               keepA1.z - oO2, keepA1.w - oO3));
        }

        hist2 = hist1; hist1 = cur;
        keepB2 = keepB1; keepB1 = rawB; keepA1 = rawA;
    }
}

// ---------------------------------------------------------------------------
// Block-tiled fused kernel (small levels) — TCY templated; block (18, TCY/2+2).
// ---------------------------------------------------------------------------
template <int Hc, int Wc, int TCY>
__global__ __launch_bounds__(18 * (TCY / 2 + 2), 3) void fused_small_kernel(
    const float* __restrict__ fine,
    float* __restrict__ coarse_out,
    float* __restrict__ lap_out)
{
    constexpr int H = 2 * Hc, W = 2 * Wc;
    constexpr int TCX = 64;
    constexpr int IY = TCY / 2;
    __shared__ float sc[TCY + 4][73];

    const int gx = threadIdx.x;
    const int iy = threadIdx.y;
    const int img = blockIdx.z;
    const int c0y = blockIdx.y * TCY;
    const int c0x = blockIdx.x * TCX;
    const int ci0 = c0y + 2 * (iy - 1);
    const int cj0 = c0x + 4 * (gx - 1);

    const int ci0c = ci0 < 0 ? 0 : (ci0 > Hc - 2 ? Hc - 2 : ci0);
    const int cj0c = cj0 < 0 ? 0 : (cj0 > Wc - 4 ? Wc - 4 : cj0);
    const bool topE   = (ci0 < 0);
    const bool botE   = (ci0 > Hc - 2);
    const bool lColE  = (cj0 < 0);
    const bool rColE  = (cj0 > Wc - 4);

    const float* fp = fine + (size_t)img * H * W;
    const bool leftE  = (cj0c == 0);
    const bool rightE = (cj0c == Wc - 4);
    const int cbase = 2 * cj0c - 4;

    const float hw0 = 0.0625f, hw1 = 0.25f, hw2 = 0.375f;
    const float hwv[5] = {hw0, hw1, hw2, hw1, hw0};

    float acc0[4] = {0.f, 0.f, 0.f, 0.f};
    float acc1[4] = {0.f, 0.f, 0.f, 0.f};
    float sfr[4][8];

#pragma unroll
    for (int a = 0; a < 7; a++) {
        int r = 2 * ci0c - 2 + a;
        r = r < 0 ? 0 : (r >= H ? H - 1 : r);
        const float* rp = fp + (size_t)r * W;

        float buf[16];
        if (!leftE) {
            float4 q = *(const float4*)(rp + cbase);
            buf[0] = q.x; buf[1] = q.y; buf[2] = q.z; buf[3] = q.w;
        }
        {
            float4 q = *(const float4*)(rp + cbase + 4);
            buf[4] = q.x; buf[5] = q.y; buf[6] = q.z; buf[7] = q.w;
            float4 p = *(const float4*)(rp + cbase + 8);
            buf[8] = p.x; buf[9] = p.y; buf[10] = p.z; buf[11] = p.w;
        }
        if (!rightE) {
            float4 q = *(const float4*)(rp + cbase + 12);
            buf[12] = q.x; buf[13] = q.y; buf[14] = q.z; buf[15] = q.w;
        } else {
            buf[12] = buf[11];
        }
        if (leftE) { buf[2] = buf[4]; buf[3] = buf[4]; }

        float hv[4];
#pragma unroll
        for (int t = 0; t < 4; t++) {
            hv[t] = fmaf(hw0, buf[2 + 2 * t] + buf[6 + 2 * t],
                    fmaf(hw1, buf[3 + 2 * t] + buf[5 + 2 * t],
                         hw2 * buf[4 + 2 * t]));
        }
        if (a < 5) {
            float w = hwv[a];
#pragma unroll
            for (int t = 0; t < 4; t++) acc0[t] = fmaf(w, hv[t], acc0[t]);
        }
        if (a >= 2) {
            float w = hwv[a - 2];
#pragma unroll
            for (int t = 0; t < 4; t++) acc1[t] = fmaf(w, hv[t], acc1[t]);
        }
        if (a >= 2 && a < 6) {
#pragma unroll
            for (int k = 0; k < 8; k++) sfr[a - 2][k] = buf[4 + k];
        }
    }

    if (lColE) {
        acc0[1] = acc0[0]; acc0[2] = acc0[0]; acc0[3] = acc0[0];
        acc1[1] = acc1[0]; acc1[2] = acc1[0]; acc1[3] = acc1[0];
    }
    if (rColE) {
        acc0[0] = acc0[3]; acc0[1] = acc0[3]; acc0[2] = acc0[3];
        acc1[0] = acc1[3]; acc1[1] = acc1[3]; acc1[2] = acc1[3];
    }

    {
        const int sr = 2 * iy, scl = 4 * gx;
#pragma unroll
        for (int t = 0; t < 4; t++) {
            float v0 = topE ? acc0[t] : (botE ? acc1[t] : acc0[t]);
            float v1 = topE ? acc0[t] : acc1[t];
            sc[sr][scl + t] = v0;
            sc[sr + 1][scl + t] = v1;
        }
    }

    const bool inner = (iy >= 1) && (iy <= IY) && (gx >= 1) && (gx <= 16);

    if (inner) {
        float* cop = coarse_out + (size_t)img * Hc * Wc;
        *(float4*)(cop + (size_t)ci0 * Wc + cj0) =
            make_float4(acc0[0], acc0[1], acc0[2], acc0[3]);
        *(float4*)(cop + (size_t)(ci0 + 1) * Wc + cj0) =
            make_float4(acc1[0], acc1[1], acc1[2], acc1[3]);
    }

    __syncthreads();

    if (inner) {
        float c4[4][6];
#pragma unroll
        for (int r = 0; r < 4; r++)
#pragma unroll
            for (int k = 0; k < 6; k++)
                c4[r][k] = sc[(2 * iy - 1) + r][(4 * gx - 1) + k];

        float* lop = lap_out + (size_t)img * H * W;

#pragma unroll
        for (int p = 0; p < 2; p++) {
            float rowE[6], rowO[6];
#pragma unroll
            for (int k = 0; k < 6; k++) {
                rowE[k] = fmaf(0.75f, c4[p + 1][k], 0.125f * (c4[p][k] + c4[p + 2][k]));
                rowO[k] = 0.5f * (c4[p + 1][k] + c4[p + 2][k]);
            }
            float oE[8], oO[8];
#pragma unroll
            for (int t = 0; t < 4; t++) {
                oE[2 * t]     = fmaf(0.75f, rowE[t + 1], 0.125f * (rowE[t] + rowE[t + 2]));
                oE[2 * t + 1] = 0.5f * (rowE[t + 1] + rowE[t + 2]);
                oO[2 * t]     = fmaf(0.75f, rowO[t + 1], 0.125f * (rowO[t] + rowO[t + 2]));
                oO[2 * t + 1] = 0.5f * (rowO[t + 1] + rowO[t + 2]);
            }

            const float* fE = sfr[2 * p];
            const float* fO = sfr[2 * p + 1];
            size_t top = (size_t)(2 * (ci0 + p)) * W + 2 * cj0;
            size_t bot = top + W;

            __stcs((float4*)(lop + top),
                   make_float4(fE[0] - oE[0], fE[1] - oE[1], fE[2] - oE[2], fE[3] - oE[3]));
            __stcs((float4*)(lop + top + 4),
                   make_float4(fE[4] - oE[4], fE[5] - oE[5], fE[6] - oE[6], fE[7] - oE[7]));
            __stcs((float4*)(lop + bot),
                   make_float4(fO[0] - oO[0], fO[1] - oO[1], fO[2] - oO[2], fO[3] - oO[3]));
            __stcs((float4*)(lop + bot + 4),
                   make_float4(fO[4] - oO[4], fO[5] - oO[5], fO[6] - oO[6], fO[7] - oO[7]));
        }
    }
}

extern "C" void kernel_launch(void* const* d_in, const int* in_sizes, int n_in,
                              void* d_out, int out_size) {
    const float* im = (const float*)d_in[0];
    float* out = (float*)d_out;

    float* g1; float* g2; float* g3;
    cudaGetSymbolAddress((void**)&g1, g_g1);
    cudaGetSymbolAddress((void**)&g2, g_g2);
    cudaGetSymbolAddress((void**)&g3, g_g3);

    const long long off0 = 0;
    const long long off1 = off0 + (long long)NIMG * 1024 * 1024;
    const long long off2 = off1 + (long long)NIMG * 512 * 512;
    const long long off3 = off2 + (long long)NIMG * 256 * 256;
    const long long off4 = off3 + (long long)NIMG * 128 * 128;

    dim3 wblock(32, 8);  // 8 warps per CTA

    // level 0: 8 strips x 8 segs = 64 warps/image -> grid.x=8 (SEG=64)
    lpyr_warp_kernel<512, 512, 64><<<dim3(8, 1, NIMG), wblock>>>(im, g1, out + off0);
    // level 1: 4 strips x 16 segs = 64 warps/image -> grid.x=8 (SEG=16)
    lpyr_warp_kernel<256, 256, 16><<<dim3(8, 1, NIMG), wblock>>>(g1, g2, out + off1);
    // level 2: fused block-tiled, TCY=16
    fused_small_kernel<128, 128, 16><<<dim3(2, 8, NIMG), dim3(18, 10)>>>(g2, g3, out + off2);
    // level 3: fused block-tiled, TCY=8 (384 CTAs); g4 = lpyr[4]
    fused_small_kernel<64, 64, 8><<<dim3(1, 8, NIMG), dim3(18, 6)>>>(g3, out + off4, out + off3);
}

// round 16
// speedup vs baseline: 1.1371x; 1.1371x over previous
#include <cuda_runtime.h>

// Laplacian pyramid, 5 levels, (16,3,1024,1024) fp32, edge-clamp padding.
// Levels 0-1: warp-persistent sliding-window kernel, software-pipelined
// (depth-1 prefetch). Level 0 SEG=32 (768 CTAs, full residency), level 1 SEG=8.
// Levels 2-3: block-tiled fused kernel, TCY=8 (max CTA count for latency tails).

#define NIMG 48  // 16 * 3

__device__ float g_g1[NIMG * 512 * 512];
__device__ float g_g2[NIMG * 256 * 256];
__device__ float g_g3[NIMG * 128 * 128];

// ---------------------------------------------------------------------------
// Warp-persistent pipelined kernel (big levels).
// ---------------------------------------------------------------------------
template <int Hc, int Wc, int SEG>
__global__ __launch_bounds__(256) void lpyr_warp_kernel(
    const float* __restrict__ fine,
    float* __restrict__ coarse_out,
    float* __restrict__ lap_out)
{
    constexpr int H = 2 * Hc, W = 2 * Wc;
    constexpr int NSTRIP = Wc / 64;            // 128 fine cols per strip

    const int lane = threadIdx.x;
    const int wg   = blockIdx.x * 8 + threadIdx.y;
    const int strip = wg % NSTRIP;
    const int seg   = wg / NSTRIP;
    const int img   = blockIdx.z;
    const int r0    = seg * SEG;
    const int base_f = strip * 128;
    const bool stripL = (strip == 0);
    const bool stripR = (strip == NSTRIP - 1);

    const float* fp = fine + (size_t)img * H * W;
    float* cop = coarse_out + (size_t)img * Hc * Wc;
    float* lop = lap_out + (size_t)img * H * W;

    const float h0 = 0.0625f, h1 = 0.25f, h2 = 0.375f;
    const float hwv[5] = {h0, h1, h2, h1, h0};

    auto loadraw = [&](int r, float4& raw, float4& eraw) {
        r = r < 0 ? 0 : (r >= H ? H - 1 : r);
        const float* rp = fp + (size_t)r * W + base_f;
        raw = *(const float4*)(rp + 4 * lane);
        if (lane == 0 && !stripL)  eraw = *(const float4*)(rp - 4);
        if (lane == 31 && !stripR) eraw = *(const float4*)(rp + 128);
    };

    auto filterrow = [&](float4 buf, float4 er, float& hv0, float& hv1, float& hvE) {
        float4 eL = make_float4(buf.x, buf.x, buf.x, buf.x);
        float4 eR = make_float4(buf.w, buf.w, buf.w, buf.w);
        if (lane == 0 && !stripL)  eL = er;
        if (lane == 31 && !stripR) eR = er;
        float xl2 = __shfl_up_sync(0xffffffffu, buf.z, 1);
        float xl1 = __shfl_up_sync(0xffffffffu, buf.w, 1);
        float xr1 = __shfl_down_sync(0xffffffffu, buf.x, 1);
        if (lane == 0)  { xl2 = eL.z; xl1 = eL.w; }
        if (lane == 31) { xr1 = eR.x; }
        hv0 = fmaf(h0, xl2 + buf.z, fmaf(h1, xl1 + buf.y, h2 * buf.x));
        hv1 = fmaf(h0, buf.x + xr1, fmaf(h1, buf.y + buf.w, h2 * buf.z));
        float hvEL = fmaf(h0, eL.x + buf.x, fmaf(h1, eL.y + eL.w, h2 * eL.z));
        float hvER = fmaf(h0, buf.z + eR.z, fmaf(h1, buf.w + eR.y, h2 * eR.x));
        hvE = (lane == 31) ? hvER : hvEL;
    };

    float wh0[5], wh1[5], whE[5];
    float4 keepA1, keepB1, keepB2;

    {
        float4 rtmp, etmp;
#pragma unroll
        for (int a = 0; a < 5; a++) {
            loadraw(2 * r0 - 4 + a, rtmp, etmp);
            filterrow(rtmp, etmp, wh0[a], wh1[a], whE[a]);
        }
        keepB1 = rtmp;
        keepA1 = rtmp; keepB2 = rtmp;
    }

    float4 hist1, hist2;
    {
        float c0 = 0.f, c1 = 0.f, cE = 0.f;
#pragma unroll
        for (int a = 0; a < 5; a++) {
            c0 = fmaf(hwv[a], wh0[a], c0);
            c1 = fmaf(hwv[a], wh1[a], c1);
            cE = fmaf(hwv[a], whE[a], cE);
        }
        float cLh = __shfl_up_sync(0xffffffffu, c1, 1);
        float cRh = __shfl_down_sync(0xffffffffu, c0, 1);
        if (lane == 0)  cLh = stripL ? c0 : cE;
        if (lane == 31) cRh = stripR ? c1 : cE;
        hist1 = make_float4(cLh, c0, c1, cRh);
        hist2 = hist1;
    }

    // depth-1 software pipeline: loads for iteration ci already in flight
    float4 nA, nB, nAe, nBe;
    loadraw(2 * r0 + 1, nA, nAe);
    loadraw(2 * r0 + 2, nB, nBe);

#pragma unroll 1
    for (int ci = r0; ci <= r0 + SEG; ci++) {
        float4 rawA = nA, rawB = nB, rAe = nAe, rBe = nBe;
        if (ci < r0 + SEG) {                   // prefetch next iteration
            loadraw(2 * ci + 3, nA, nAe);
            loadraw(2 * ci + 4, nB, nBe);
        }

        float a0, a1, aE, b0, b1, bE;
        filterrow(rawA, rAe, a0, a1, aE);
        filterrow(rawB, rBe, b0, b1, bE);

        wh0[0] = wh0[2]; wh0[1] = wh0[3]; wh0[2] = wh0[4]; wh0[3] = a0; wh0[4] = b0;
        wh1[0] = wh1[2]; wh1[1] = wh1[3]; wh1[2] = wh1[4]; wh1[3] = a1; wh1[4] = b1;
        whE[0] = whE[2]; whE[1] = whE[3]; whE[2] = whE[4]; whE[3] = aE; whE[4] = bE;

        float c0 = 0.f, c1 = 0.f, cE = 0.f;
#pragma unroll
        for (int a = 0; a < 5; a++) {
            c0 = fmaf(hwv[a], wh0[a], c0);
            c1 = fmaf(hwv[a], wh1[a], c1);
            cE = fmaf(hwv[a], whE[a], cE);
        }
        float cLh = __shfl_up_sync(0xffffffffu, c1, 1);
        float cRh = __shfl_down_sync(0xffffffffu, c0, 1);
        if (lane == 0)  cLh = stripL ? c0 : cE;   // image edge: clamp on COARSE grid
        if (lane == 31) cRh = stripR ? c1 : cE;
        float4 cur = make_float4(cLh, c0, c1, cRh);

        if (ci < r0 + SEG)
            *(float2*)(cop + (size_t)ci * Wc + (base_f >> 1) + 2 * lane) =
                make_float2(c0, c1);

        if (ci > r0) {
            const int cp = ci - 1;
            float4 A = (cp == 0) ? hist1 : hist2;
            float4 B = hist1;
            float4 C = (cp == Hc - 1) ? hist1 : cur;

            float rE0 = fmaf(0.125f, A.x + C.x, 0.75f * B.x);
            float rE1 = fmaf(0.125f, A.y + C.y, 0.75f * B.y);
            float rE2 = fmaf(0.125f, A.z + C.z, 0.75f * B.z);
            float rE3 = fmaf(0.125f, A.w + C.w, 0.75f * B.w);
            float rO0 = 0.5f * (B.x + C.x);
            float rO1 = 0.5f * (B.y + C.y);
            float rO2 = 0.5f * (B.z + C.z);
            float rO3 = 0.5f * (B.w + C.w);

            float oE0 = fmaf(0.125f, rE0 + rE2, 0.75f * rE1);
            float oE1 = 0.5f * (rE1 + rE2);
            float oE2 = fmaf(0.125f, rE1 + rE3, 0.75f * rE2);
            float oE3 = 0.5f * (rE2 + rE3);
            float oO0 = fmaf(0.125f, rO0 + rO2, 0.75f * rO1);
            float oO1 = 0.5f * (rO1 + rO2);
            float oO2 = fmaf(0.125f, rO1 + rO3, 0.75f * rO2);
            float oO3 = 0.5f * (rO2 + rO3);

            size_t top = (size_t)(2 * cp) * W + base_f + 4 * lane;
            __stcs((float4*)(lop + top),
                   make_float4(keepB2.x - oE0, keepB2.y - oE1,
                               keepB2.z - oE2, keepB2.w - oE3));
            __stcs((float4*)(lop + top + W),
                   make_float4(keepA1.x - oO0, keepA1.y - oO1,
                               keepA1.z - oO2, keepA1.w - oO3));
        }

        hist2 = hist1; hist1 = cur;
        keepB2 = keepB1; keepB1 = rawB; keepA1 = rawA;
    }
}

// ---------------------------------------------------------------------------
// Block-tiled fused kernel (small levels) — TCY templated; block (18, TCY/2+2).
// ---------------------------------------------------------------------------
template <int Hc, int Wc, int TCY>
__global__ __launch_bounds__(18 * (TCY / 2 + 2), 3) void fused_small_kernel(
    const float* __restrict__ fine,
    float* __restrict__ coarse_out,
    float* __restrict__ lap_out)
{
    constexpr int H = 2 * Hc, W = 2 * Wc;
    constexpr int TCX = 64;
    constexpr int IY = TCY / 2;
    __shared__ float sc[TCY + 4][73];

    const int gx = threadIdx.x;
    const int iy = threadIdx.y;
    const int img = blockIdx.z;
    const int c0y = blockIdx.y * TCY;
    const int c0x = blockIdx.x * TCX;
    const int ci0 = c0y + 2 * (iy - 1);
    const int cj0 = c0x + 4 * (gx - 1);

    const int ci0c = ci0 < 0 ? 0 : (ci0 > Hc - 2 ? Hc - 2 : ci0);
    const int cj0c = cj0 < 0 ? 0 : (cj0 > Wc - 4 ? Wc - 4 : cj0);
    const bool topE   = (ci0 < 0);
    const bool botE   = (ci0 > Hc - 2);
    const bool lColE  = (cj0 < 0);
    const bool rColE  = (cj0 > Wc - 4);

    const float* fp = fine + (size_t)img * H * W;
    const bool leftE  = (cj0c == 0);
    const bool rightE = (cj0c == Wc - 4);
    const int cbase = 2 * cj0c - 4;

    const float hw0 = 0.0625f, hw1 = 0.25f, hw2 = 0.375f;
    const float hwv[5] = {hw0, hw1, hw2, hw1, hw0};

    float acc0[4] = {0.f, 0.f, 0.f, 0.f};
    float acc1[4] = {0.f, 0.f, 0.f, 0.f};
    float sfr[4][8];

#pragma unroll
    for (int a = 0; a < 7; a++) {
        int r = 2 * ci0c - 2 + a;
        r = r < 0 ? 0 : (r >= H ? H - 1 : r);
        const float* rp = fp + (size_t)r * W;

        float buf[16];
        if (!leftE) {
            float4 q = *(const float4*)(rp + cbase);
            buf[0] = q.x; buf[1] = q.y; buf[2] = q.z; buf[3] = q.w;
        }
        {
            float4 q = *(const float4*)(rp + cbase + 4);
            buf[4] = q.x; buf[5] = q.y; buf[6] = q.z; buf[7] = q.w;
            float4 p = *(const float4*)(rp + cbase + 8);
            buf[8] = p.x; buf[9] = p.y; buf[10] = p.z; buf[11] = p.w;
        }
        if (!rightE) {
            float4 q = *(const float4*)(rp + cbase + 12);
            buf[12] = q.x; buf[13] = q.y; buf[14] = q.z; buf[15] = q.w;
        } else {
            buf[12] = buf[11];
        }
        if (leftE) { buf[2] = buf[4]; buf[3] = buf[4]; }

        float hv[4];
#pragma unroll
        for (int t = 0; t < 4; t++) {
            hv[t] = fmaf(hw0, buf[2 + 2 * t] + buf[6 + 2 * t],
                    fmaf(hw1, buf[3 + 2 * t] + buf[5 + 2 * t],
                         hw2 * buf[4 + 2 * t]));
        }
        if (a < 5) {
            float w = hwv[a];
#pragma unroll
            for (int t = 0; t < 4; t++) acc0[t] = fmaf(w, hv[t], acc0[t]);
        }
        if (a >= 2) {
            float w = hwv[a - 2];
#pragma unroll
            for (int t = 0; t < 4; t++) acc1[t] = fmaf(w, hv[t], acc1[t]);
        }
        if (a >= 2 && a < 6) {
#pragma unroll
            for (int k = 0; k < 8; k++) sfr[a - 2][k] = buf[4 + k];
        }
    }

    if (lColE) {
        acc0[1] = acc0[0]; acc0[2] = acc0[0]; acc0[3] = acc0[0];
        acc1[1] = acc1[0]; acc1[2] = acc1[0]; acc1[3] = acc1[0];
    }
    if (rColE) {
        acc0[0] = acc0[3]; acc0[1] = acc0[3]; acc0[2] = acc0[3];
        acc1[0] = acc1[3]; acc1[1] = acc1[3]; acc1[2] = acc1[3];
    }

    {
        const int sr = 2 * iy, scl = 4 * gx;
#pragma unroll
        for (int t = 0; t < 4; t++) {
            float v0 = topE ? acc0[t] : (botE ? acc1[t] : acc0[t]);
            float v1 = topE ? acc0[t] : acc1[t];
            sc[sr][scl + t] = v0;
            sc[sr + 1][scl + t] = v1;
        }
    }

    const bool inner = (iy >= 1) && (iy <= IY) && (gx >= 1) && (gx <= 16);

    if (inner) {
        float* cop = coarse_out + (size_t)img * Hc * Wc;
        *(float4*)(cop + (size_t)ci0 * Wc + cj0) =
            make_float4(acc0[0], acc0[1], acc0[2], acc0[3]);
        *(float4*)(cop + (size_t)(ci0 + 1) * Wc + cj0) =
            make_float4(acc1[0], acc1[1], acc1[2], acc1[3]);
    }

    __syncthreads();

    if (inner) {
        float c4[4][6];
#pragma unroll
        for (int r = 0; r < 4; r++)
#pragma unroll
            for (int k = 0; k < 6; k++)
                c4[r][k] = sc[(2 * iy - 1) + r][(4 * gx - 1) + k];

        float* lop = lap_out + (size_t)img * H * W;

#pragma unroll
        for (int p = 0; p < 2; p++) {
            float rowE[6], rowO[6];
#pragma unroll
            for (int k = 0; k < 6; k++) {
                rowE[k] = fmaf(0.75f, c4[p + 1][k], 0.125f * (c4[p][k] + c4[p + 2][k]));
                rowO[k] = 0.5f * (c4[p + 1][k] + c4[p + 2][k]);
            }
            float oE[8], oO[8];
#pragma unroll
            for (int t = 0; t < 4; t++) {
                oE[2 * t]     = fmaf(0.75f, rowE[t + 1], 0.125f * (rowE[t] + rowE[t + 2]));
                oE[2 * t + 1] = 0.5f * (rowE[t + 1] + rowE[t + 2]);
                oO[2 * t]     = fmaf(0.75f, rowO[t + 1], 0.125f * (rowO[t] + rowO[t + 2]));
                oO[2 * t + 1] = 0.5f * (rowO[t + 1] + rowO[t + 2]);
            }

            const float* fE = sfr[2 * p];
            const float* fO = sfr[2 * p + 1];
            size_t top = (size_t)(2 * (ci0 + p)) * W + 2 * cj0;
            size_t bot = top + W;

            __stcs((float4*)(lop + top),
                   make_float4(fE[0] - oE[0], fE[1] - oE[1], fE[2] - oE[2], fE[3] - oE[3]));
            __stcs((float4*)(lop + top + 4),
                   make_float4(fE[4] - oE[4], fE[5] - oE[5], fE[6] - oE[6], fE[7] - oE[7]));
            __stcs((float4*)(lop + bot),
                   make_float4(fO[0] - oO[0], fO[1] - oO[1], fO[2] - oO[2], fO[3] - oO[3]));
            __stcs((float4*)(lop + bot + 4),
                   make_float4(fO[4] - oO[4], fO[5] - oO[5], fO[6] - oO[6], fO[7] - oO[7]));
        }
    }
}

extern "C" void kernel_launch(void* const* d_in, const int* in_sizes, int n_in,
                              void* d_out, int out_size) {
    const float* im = (const float*)d_in[0];
    float* out = (float*)d_out;

    float* g1; float* g2; float* g3;
    cudaGetSymbolAddress((void**)&g1, g_g1);
    cudaGetSymbolAddress((void**)&g2, g_g2);
    cudaGetSymbolAddress((void**)&g3, g_g3);

    const long long off0 = 0;
    const long long off1 = off0 + (long long)NIMG * 1024 * 1024;
    const long long off2 = off1 + (long long)NIMG * 512 * 512;
    const long long off3 = off2 + (long long)NIMG * 256 * 256;
    const long long off4 = off3 + (long long)NIMG * 128 * 128;

    dim3 wblock(32, 8);  // 8 warps per CTA

    // level 0: 8 strips x 16 segs = 128 warps/image -> grid.x=16 (SEG=32)
    lpyr_warp_kernel<512, 512, 32><<<dim3(16, 1, NIMG), wblock>>>(im, g1, out + off0);
    // level 1: 4 strips x 32 segs = 128 warps/image -> grid.x=16 (SEG=8)
    lpyr_warp_kernel<256, 256, 8><<<dim3(16, 1, NIMG), wblock>>>(g1, g2, out + off1);
    // level 2: fused block-tiled, TCY=8 (1536 CTAs)
    fused_small_kernel<128, 128, 8><<<dim3(2, 16, NIMG), dim3(18, 6)>>>(g2, g3, out + off2);
    // level 3: fused block-tiled, TCY=8 (384 CTAs); g4 = lpyr[4]
    fused_small_kernel<64, 64, 8><<<dim3(1, 8, NIMG), dim3(18, 6)>>>(g3, out + off4, out + off3);
}

// round 17
// speedup vs baseline: 1.1388x; 1.0016x over previous
#include <cuda_runtime.h>

// Laplacian pyramid, 5 levels, (16,3,1024,1024) fp32, edge-clamp padding.
// Levels 0-1: warp-persistent sliding-window kernel, software-pipelined
// (depth-1 prefetch), main loop unrolled x2 so ptxas renames the sliding
// window instead of emitting rotation MOVs. Level 0 SEG=32, level 1 SEG=8.
// Levels 2-3: block-tiled fused kernel, TCY=8.

#define NIMG 48  // 16 * 3

__device__ float g_g1[NIMG * 512 * 512];
__device__ float g_g2[NIMG * 256 * 256];
__device__ float g_g3[NIMG * 128 * 128];

// ---------------------------------------------------------------------------
// Warp-persistent pipelined kernel (big levels).
// ---------------------------------------------------------------------------
template <int Hc, int Wc, int SEG>
__global__ __launch_bounds__(256) void lpyr_warp_kernel(
    const float* __restrict__ fine,
    float* __restrict__ coarse_out,
    float* __restrict__ lap_out)
{
    constexpr int H = 2 * Hc, W = 2 * Wc;
    constexpr int NSTRIP = Wc / 64;            // 128 fine cols per strip

    const int lane = threadIdx.x;
    const int wg   = blockIdx.x * 8 + threadIdx.y;
    const int strip = wg % NSTRIP;
    const int seg   = wg / NSTRIP;
    const int img   = blockIdx.z;
    const int r0    = seg * SEG;
    const int base_f = strip * 128;
    const bool stripL = (strip == 0);
    const bool stripR = (strip == NSTRIP - 1);

    const float* fp = fine + (size_t)img * H * W;
    float* cop = coarse_out + (size_t)img * Hc * Wc;
    float* lop = lap_out + (size_t)img * H * W;

    const float h0 = 0.0625f, h1 = 0.25f, h2 = 0.375f;
    const float hwv[5] = {h0, h1, h2, h1, h0};

    auto loadraw = [&](int r, float4& raw, float4& eraw) {
        r = r < 0 ? 0 : (r >= H ? H - 1 : r);
        const float* rp = fp + (size_t)r * W + base_f;
        raw = *(const float4*)(rp + 4 * lane);
        if (lane == 0 && !stripL)  eraw = *(const float4*)(rp - 4);
        if (lane == 31 && !stripR) eraw = *(const float4*)(rp + 128);
    };

    auto filterrow = [&](float4 buf, float4 er, float& hv0, float& hv1, float& hvE) {
        float4 eL = make_float4(buf.x, buf.x, buf.x, buf.x);
        float4 eR = make_float4(buf.w, buf.w, buf.w, buf.w);
        if (lane == 0 && !stripL)  eL = er;
        if (lane == 31 && !stripR) eR = er;
        float xl2 = __shfl_up_sync(0xffffffffu, buf.z, 1);
        float xl1 = __shfl_up_sync(0xffffffffu, buf.w, 1);
        float xr1 = __shfl_down_sync(0xffffffffu, buf.x, 1);
        if (lane == 0)  { xl2 = eL.z; xl1 = eL.w; }
        if (lane == 31) { xr1 = eR.x; }
        hv0 = fmaf(h0, xl2 + buf.z, fmaf(h1, xl1 + buf.y, h2 * buf.x));
        hv1 = fmaf(h0, buf.x + xr1, fmaf(h1, buf.y + buf.w, h2 * buf.z));
        float hvEL = fmaf(h0, eL.x + buf.x, fmaf(h1, eL.y + eL.w, h2 * eL.z));
        float hvER = fmaf(h0, buf.z + eR.z, fmaf(h1, buf.w + eR.y, h2 * eR.x));
        hvE = (lane == 31) ? hvER : hvEL;
    };

    float wh0[5], wh1[5], whE[5];
    float4 keepA1, keepB1, keepB2;

    {
        float4 rtmp, etmp;
#pragma unroll
        for (int a = 0; a < 5; a++) {
            loadraw(2 * r0 - 4 + a, rtmp, etmp);
            filterrow(rtmp, etmp, wh0[a], wh1[a], whE[a]);
        }
        keepB1 = rtmp;
        keepA1 = rtmp; keepB2 = rtmp;
    }

    float4 hist1, hist2;
    {
        float c0 = 0.f, c1 = 0.f, cE = 0.f;
#pragma unroll
        for (int a = 0; a < 5; a++) {
            c0 = fmaf(hwv[a], wh0[a], c0);
            c1 = fmaf(hwv[a], wh1[a], c1);
            cE = fmaf(hwv[a], whE[a], cE);
        }
        float cLh = __shfl_up_sync(0xffffffffu, c1, 1);
        float cRh = __shfl_down_sync(0xffffffffu, c0, 1);
        if (lane == 0)  cLh = stripL ? c0 : cE;
        if (lane == 31) cRh = stripR ? c1 : cE;
        hist1 = make_float4(cLh, c0, c1, cRh);
        hist2 = hist1;
    }

    // depth-1 software pipeline: loads for iteration ci already in flight
    float4 nA, nB, nAe, nBe;
    loadraw(2 * r0 + 1, nA, nAe);
    loadraw(2 * r0 + 2, nB, nBe);

#pragma unroll 2
    for (int ci = r0; ci <= r0 + SEG; ci++) {
        float4 rawA = nA, rawB = nB, rAe = nAe, rBe = nBe;
        if (ci < r0 + SEG) {                   // prefetch next iteration
            loadraw(2 * ci + 3, nA, nAe);
            loadraw(2 * ci + 4, nB, nBe);
        }

        float a0, a1, aE, b0, b1, bE;
        filterrow(rawA, rAe, a0, a1, aE);
        filterrow(rawB, rBe, b0, b1, bE);

        wh0[0] = wh0[2]; wh0[1] = wh0[3]; wh0[2] = wh0[4]; wh0[3] = a0; wh0[4] = b0;
        wh1[0] = wh1[2]; wh1[1] = wh1[3]; wh1[2] = wh1[4]; wh1[3] = a1; wh1[4] = b1;
        whE[0] = whE[2]; whE[1] = whE[3]; whE[2] = whE[4]; whE[3] = aE; whE[4] = bE;

        float c0 = 0.f, c1 = 0.f, cE = 0.f;
#pragma unroll
        for (int a = 0; a < 5; a++) {
            c0 = fmaf(hwv[a], wh0[a], c0);
            c1 = fmaf(hwv[a], wh1[a], c1);
            cE = fmaf(hwv[a], whE[a], cE);
        }
        float cLh = __shfl_up_sync(0xffffffffu, c1, 1);
        float cRh = __shfl_down_sync(0xffffffffu, c0, 1);
        if (lane == 0)  cLh = stripL ? c0 : cE;   // image edge: clamp on COARSE grid
        if (lane == 31) cRh = stripR ? c1 : cE;
        float4 cur = make_float4(cLh, c0, c1, cRh);

        if (ci < r0 + SEG)
            *(float2*)(cop + (size_t)ci * Wc + (base_f >> 1) + 2 * lane) =
                make_float2(c0, c1);

        if (ci > r0) {
            const int cp = ci - 1;
            float4 A = (cp == 0) ? hist1 : hist2;
            float4 B = hist1;
            float4 C = (cp == Hc - 1) ? hist1 : cur;

            float rE0 = fmaf(0.125f, A.x + C.x, 0.75f * B.x);
            float rE1 = fmaf(0.125f, A.y + C.y, 0.75f * B.y);
            float rE2 = fmaf(0.125f, A.z + C.z, 0.75f * B.z);
            float rE3 = fmaf(0.125f, A.w + C.w, 0.75f * B.w);
            float rO0 = 0.5f * (B.x + C.x);
            float rO1 = 0.5f * (B.y + C.y);
            float rO2 = 0.5f * (B.z + C.z);
            float rO3 = 0.5f * (B.w + C.w);

            float oE0 = fmaf(0.125f, rE0 + rE2, 0.75f * rE1);
            float oE1 = 0.5f * (rE1 + rE2);
            float oE2 = fmaf(0.125f, rE1 + rE3, 0.75f * rE2);
            float oE3 = 0.5f * (rE2 + rE3);
            float oO0 = fmaf(0.125f, rO0 + rO2, 0.75f * rO1);
            float oO1 = 0.5f * (rO1 + rO2);
            float oO2 = fmaf(0.125f, rO1 + rO3, 0.75f * rO2);
            float oO3 = 0.5f * (rO2 + rO3);

            size_t top = (size_t)(2 * cp) * W + base_f + 4 * lane;
            __stcs((float4*)(lop + top),
                   make_float4(keepB2.x - oE0, keepB2.y - oE1,
                               keepB2.z - oE2, keepB2.w - oE3));
            __stcs((float4*)(lop + top + W),
                   make_float4(keepA1.x - oO0, keepA1.y - oO1,
                               keepA1.z - oO2, keepA1.w - oO3));
        }

        hist2 = hist1; hist1 = cur;
        keepB2 = keepB1; keepB1 = rawB; keepA1 = rawA;
    }
}

// ---------------------------------------------------------------------------
// Block-tiled fused kernel (small levels) — TCY templated; block (18, TCY/2+2).
// ---------------------------------------------------------------------------
template <int Hc, int Wc, int TCY>
__global__ __launch_bounds__(18 * (TCY / 2 + 2), 3) void fused_small_kernel(
    const float* __restrict__ fine,
    float* __restrict__ coarse_out,
    float* __restrict__ lap_out)
{
    constexpr int H = 2 * Hc, W = 2 * Wc;
    constexpr int TCX = 64;
    constexpr int IY = TCY / 2;
    __shared__ float sc[TCY + 4][73];

    const int gx = threadIdx.x;
    const int iy = threadIdx.y;
    const int img = blockIdx.z;
    const int c0y = blockIdx.y * TCY;
    const int c0x = blockIdx.x * TCX;
    const int ci0 = c0y + 2 * (iy - 1);
    const int cj0 = c0x + 4 * (gx - 1);

    const int ci0c = ci0 < 0 ? 0 : (ci0 > Hc - 2 ? Hc - 2 : ci0);
    const int cj0c = cj0 < 0 ? 0 : (cj0 > Wc - 4 ? Wc - 4 : cj0);
    const bool topE   = (ci0 < 0);
    const bool botE   = (ci0 > Hc - 2);
    const bool lColE  = (cj0 < 0);
    const bool rColE  = (cj0 > Wc - 4);

    const float* fp = fine + (size_t)img * H * W;
    const bool leftE  = (cj0c == 0);
    const bool rightE = (cj0c == Wc - 4);
    const int cbase = 2 * cj0c - 4;

    const float hw0 = 0.0625f, hw1 = 0.25f, hw2 = 0.375f;
    const float hwv[5] = {hw0, hw1, hw2, hw1, hw0};

    float acc0[4] = {0.f, 0.f, 0.f, 0.f};
    float acc1[4] = {0.f, 0.f, 0.f, 0.f};
    float sfr[4][8];

#pragma unroll
    for (int a = 0; a < 7; a++) {
        int r = 2 * ci0c - 2 + a;
        r = r < 0 ? 0 : (r >= H ? H - 1 : r);
        const float* rp = fp + (size_t)r * W;

        float buf[16];
        if (!leftE) {
            float4 q = *(const float4*)(rp + cbase);
            buf[0] = q.x; buf[1] = q.y; buf[2] = q.z; buf[3] = q.w;
        }
        {
            float4 q = *(const float4*)(rp + cbase + 4);
            buf[4] = q.x; buf[5] = q.y; buf[6] = q.z; buf[7] = q.w;
            float4 p = *(const float4*)(rp + cbase + 8);
            buf[8] = p.x; buf[9] = p.y; buf[10] = p.z; buf[11] = p.w;
        }
        if (!rightE) {
            float4 q = *(const float4*)(rp + cbase + 12);
            buf[12] = q.x; buf[13] = q.y; buf[14] = q.z; buf[15] = q.w;
        } else {
            buf[12] = buf[11];
        }
        if (leftE) { buf[2] = buf[4]; buf[3] = buf[4]; }

        float hv[4];
#pragma unroll
        for (int t = 0; t < 4; t++) {
            hv[t] = fmaf(hw0, buf[2 + 2 * t] + buf[6 + 2 * t],
                    fmaf(hw1, buf[3 + 2 * t] + buf[5 + 2 * t],
                         hw2 * buf[4 + 2 * t]));
        }
        if (a < 5) {
            float w = hwv[a];
#pragma unroll
            for (int t = 0; t < 4; t++) acc0[t] = fmaf(w, hv[t], acc0[t]);
        }
        if (a >= 2) {
            float w = hwv[a - 2];
#pragma unroll
            for (int t = 0; t < 4; t++) acc1[t] = fmaf(w, hv[t], acc1[t]);
        }
        if (a >= 2 && a < 6) {
#pragma unroll
            for (int k = 0; k < 8; k++) sfr[a - 2][k] = buf[4 + k];
        }
    }

    if (lColE) {
        acc0[1] = acc0[0]; acc0[2] = acc0[0]; acc0[3] = acc0[0];
        acc1[1] = acc1[0]; acc1[2] = acc1[0]; acc1[3] = acc1[0];
    }
    if (rColE) {
        acc0[0] = acc0[3]; acc0[1] = acc0[3]; acc0[2] = acc0[3];
        acc1[0] = acc1[3]; acc1[1] = acc1[3]; acc1[2] = acc1[3];
    }

    {
        const int sr = 2 * iy, scl = 4 * gx;
#pragma unroll
        for (int t = 0; t < 4; t++) {
            float v0 = topE ? acc0[t] : (botE ? acc1[t] : acc0[t]);
            float v1 = topE ? acc0[t] : acc1[t];
            sc[sr][scl + t] = v0;
            sc[sr + 1][scl + t] = v1;
        }
    }

    const bool inner = (iy >= 1) && (iy <= IY) && (gx >= 1) && (gx <= 16);

    if (inner) {
        float* cop = coarse_out + (size_t)img * Hc * Wc;
        *(float4*)(cop + (size_t)ci0 * Wc + cj0) =
            make_float4(acc0[0], acc0[1], acc0[2], acc0[3]);
        *(float4*)(cop + (size_t)(ci0 + 1) * Wc + cj0) =
            make_float4(acc1[0], acc1[1], acc1[2], acc1[3]);
    }

    __syncthreads();

    if (inner) {
        float c4[4][6];
#pragma unroll
        for (int r = 0; r < 4; r++)
#pragma unroll
            for (int k = 0; k < 6; k++)
                c4[r][k] = sc[(2 * iy - 1) + r][(4 * gx - 1) + k];

        float* lop = lap_out + (size_t)img * H * W;

#pragma unroll
        for (int p = 0; p < 2; p++) {
            float rowE[6], rowO[6];
#pragma unroll
            for (int k = 0; k < 6; k++) {
                rowE[k] = fmaf(0.75f, c4[p + 1][k], 0.125f * (c4[p][k] + c4[p + 2][k]));
                rowO[k] = 0.5f * (c4[p + 1][k] + c4[p + 2][k]);
            }
            float oE[8], oO[8];
#pragma unroll
            for (int t = 0; t < 4; t++) {
                oE[2 * t]     = fmaf(0.75f, rowE[t + 1], 0.125f * (rowE[t] + rowE[t + 2]));
                oE[2 * t + 1] = 0.5f * (rowE[t + 1] + rowE[t + 2]);
                oO[2 * t]     = fmaf(0.75f, rowO[t + 1], 0.125f * (rowO[t] + rowO[t + 2]));
                oO[2 * t + 1] = 0.5f * (rowO[t + 1] + rowO[t + 2]);
            }

            const float* fE = sfr[2 * p];
            const float* fO = sfr[2 * p + 1];
            size_t top = (size_t)(2 * (ci0 + p)) * W + 2 * cj0;
            size_t bot = top + W;

            __stcs((float4*)(lop + top),
                   make_float4(fE[0] - oE[0], fE[1] - oE[1], fE[2] - oE[2], fE[3] - oE[3]));
            __stcs((float4*)(lop + top + 4),
                   make_float4(fE[4] - oE[4], fE[5] - oE[5], fE[6] - oE[6], fE[7] - oE[7]));
            __stcs((float4*)(lop + bot),
                   make_float4(fO[0] - oO[0], fO[1] - oO[1], fO[2] - oO[2], fO[3] - oO[3]));
            __stcs((float4*)(lop + bot + 4),
                   make_float4(fO[4] - oO[4], fO[5] - oO[5], fO[6] - oO[6], fO[7] - oO[7]));
        }
    }
}

extern "C" void kernel_launch(void* const* d_in, const int* in_sizes, int n_in,
                              void* d_out, int out_size) {
    const float* im = (const float*)d_in[0];
    float* out = (float*)d_out;

    float* g1; float* g2; float* g3;
    cudaGetSymbolAddress((void**)&g1, g_g1);
    cudaGetSymbolAddress((void**)&g2, g_g2);
    cudaGetSymbolAddress((void**)&g3, g_g3);

    const long long off0 = 0;
    const long long off1 = off0 + (long long)NIMG * 1024 * 1024;
    const long long off2 = off1 + (long long)NIMG * 512 * 512;
    const long long off3 = off2 + (long long)NIMG * 256 * 256;
    const long long off4 = off3 + (long long)NIMG * 128 * 128;

    dim3 wblock(32, 8);  // 8 warps per CTA

    // level 0: 8 strips x 16 segs = 128 warps/image -> grid.x=16 (SEG=32)
    lpyr_warp_kernel<512, 512, 32><<<dim3(16, 1, NIMG), wblock>>>(im, g1, out + off0);
    // level 1: 4 strips x 32 segs = 128 warps/image -> grid.x=16 (SEG=8)
    lpyr_warp_kernel<256, 256, 8><<<dim3(16, 1, NIMG), wblock>>>(g1, g2, out + off1);
    // level 2: fused block-tiled, TCY=8 (1536 CTAs)
    fused_small_kernel<128, 128, 8><<<dim3(2, 16, NIMG), dim3(18, 6)>>>(g2, g3, out + off2);
    // level 3: fused block-tiled, TCY=8 (384 CTAs); g4 = lpyr[4]
    fused_small_kernel<64, 64, 8><<<dim3(1, 8, NIMG), dim3(18, 6)>>>(g3, out + off4, out + off3);
}